// round 14
// baseline (speedup 1.0000x reference)
#include <cuda_runtime.h>
#include <cuda_bf16.h>
#include <math.h>
#include <stdint.h>

#define BATCH 8
#define NK    2048
#define EMB   512
#define RD    64

// ---------------------------------------------------------------------------
// Scratch globals (allocation-free rule)
// ---------------------------------------------------------------------------
__device__ __nv_bfloat16 g_ra[BATCH * NK * RD];     // 2 MB, scaled by 1/64
__device__ __nv_bfloat16 g_rb[BATCH * NK * RD];     // 2 MB (row-major, for sums1)
__device__ unsigned char g_rbf[BATCH * 256 * 1024]; // 2 MB rb in mma-B-fragment order
__device__ float g_maskmul[BATCH * NK];             // 1.0 valid, 0.0 masked
__device__ float g_Mpart[BATCH * 16 * 64 * 64];     // partial M per (batch, lblock)
__device__ float g_vpart[BATCH * 16 * 64];          // partial v
__device__ float g_Npart[BATCH * 16];               // partial counts
__device__ unsigned char g_Mf[BATCH * 64 * 128];    // M bf16, [c][k] 128B rows, pre-swizzled
__device__ float g_v[BATCH * 64];
__device__ float g_N[BATCH];

// ---------------------------------------------------------------------------
// Helpers
// ---------------------------------------------------------------------------
__device__ __forceinline__ uint32_t smem_u32(const void* p) {
    uint32_t a;
    asm("{ .reg .u64 t; cvta.to.shared.u64 t, %1; cvt.u32.u64 %0, t; }" : "=r"(a) : "l"(p));
    return a;
}
__device__ __forceinline__ void ldmx4(uint32_t (&r)[4], uint32_t a) {
    asm volatile("ldmatrix.sync.aligned.m8n8.x4.shared.b16 {%0,%1,%2,%3}, [%4];"
                 : "=r"(r[0]), "=r"(r[1]), "=r"(r[2]), "=r"(r[3]) : "r"(a));
}
__device__ __forceinline__ void mma16816(float (&d)[4], const uint32_t (&a)[4],
                                         uint32_t b0, uint32_t b1) {
    asm volatile("mma.sync.aligned.m16n8k16.row.col.f32.bf16.bf16.f32 "
                 "{%0,%1,%2,%3},{%4,%5,%6,%7},{%8,%9},{%0,%1,%2,%3};"
                 : "+f"(d[0]), "+f"(d[1]), "+f"(d[2]), "+f"(d[3])
                 : "r"(a[0]), "r"(a[1]), "r"(a[2]), "r"(a[3]), "r"(b0), "r"(b1));
}
__device__ __forceinline__ uint32_t bf2u(__nv_bfloat162 v) {
    return *reinterpret_cast<uint32_t*>(&v);
}

// ---------------------------------------------------------------------------
// Projection via HMMA: out[row][n] = (1/64) * sum_k in[row][k] * R[k][n]
// Bm pass also writes rb in fragment-major order (g_rbf) + padding mask.
// ---------------------------------------------------------------------------
#define PSMEM (65536 + 16384)

__global__ __launch_bounds__(256, 2) void project_kernel(const float* __restrict__ A,
                                                         const float* __restrict__ Bm,
                                                         const float* __restrict__ R) {
    extern __shared__ char ps[];
    char* s_R = ps;                 // 64 KB: [n][k] bf16, 1024B rows, sw (2k ^ ((n&7)*16))
    char* s_a = ps + 65536;         // 16 KB
    const uint32_t sR = smem_u32(s_R);
    const uint32_t sA = smem_u32(s_a);
    const int tid = threadIdx.x, lane = tid & 31, warp = tid >> 5;
    const int isB = blockIdx.y;
    const float* in = isB ? Bm : A;
    __nv_bfloat16* outp = isB ? g_rb : g_ra;
    const int rowbase = blockIdx.x * 128;

    // Convert R directly into swizzled smem
    {
        const int rn = tid & 63;
        const int rkq = tid >> 6;
        const int xn = (rn & 7) * 16;
#pragma unroll
        for (int t = 0; t < 16; t++) {
            int k = rkq * 128 + t * 8;
            float f0 = R[(size_t)(k + 0) * 64 + rn], f1 = R[(size_t)(k + 1) * 64 + rn];
            float f2 = R[(size_t)(k + 2) * 64 + rn], f3 = R[(size_t)(k + 3) * 64 + rn];
            float f4 = R[(size_t)(k + 4) * 64 + rn], f5 = R[(size_t)(k + 5) * 64 + rn];
            float f6 = R[(size_t)(k + 6) * 64 + rn], f7 = R[(size_t)(k + 7) * 64 + rn];
            uint4 pk;
            pk.x = bf2u(__floats2bfloat162_rn(f0, f1));
            pk.y = bf2u(__floats2bfloat162_rn(f2, f3));
            pk.z = bf2u(__floats2bfloat162_rn(f4, f5));
            pk.w = bf2u(__floats2bfloat162_rn(f6, f7));
            *(uint4*)(s_R + rn * 1024 + ((2 * k) ^ xn)) = pk;
        }
    }

    const int rb0 = tid >> 4;
    const int qf  = tid & 15;
    const int axf = (rb0 & 7) * 16;

    uint4 pf[8];
    unsigned nzf[8];
#pragma unroll
    for (int i = 0; i < 8; i++) nzf[i] = 0u;
#pragma unroll
    for (int i = 0; i < 8; i++)
        pf[i] = *(const uint4*)(in + (size_t)(rowbase + rb0 + 16 * i) * EMB + qf * 4);

    float acc[8][4];
#pragma unroll
    for (int nt = 0; nt < 8; nt++)
#pragma unroll
        for (int j = 0; j < 4; j++) acc[nt][j] = 0.f;

    const int a_row = warp * 16 + (lane & 15);
    const uint32_t a_base = sA + a_row * 128;
    const int a_x  = (a_row & 7) * 16;
    const int a_kb = (lane >> 4) * 16;
    const int b_m = lane >> 3, b_r = lane & 7;
    const int b_nl = (b_m >> 1) * 8 + b_r;
    const int b_kb = (b_m & 1) * 16;
    const int b_x  = b_r * 16;

    for (int kc = 0; kc < 8; kc++) {
        __syncthreads();
#pragma unroll
        for (int i = 0; i < 8; i++) {
            int row = rb0 + 16 * i;
            float4 v = *(float4*)&pf[i];
            nzf[i] |= (__float_as_uint(v.x) | __float_as_uint(v.y) |
                       __float_as_uint(v.z) | __float_as_uint(v.w)) & 0x7FFFFFFFu;
            __nv_bfloat162 p0 = __floats2bfloat162_rn(v.x, v.y);
            __nv_bfloat162 p1 = __floats2bfloat162_rn(v.z, v.w);
            *(uint2*)(s_a + row * 128 + ((qf * 8) ^ axf)) = make_uint2(bf2u(p0), bf2u(p1));
        }
        if (kc < 7) {
#pragma unroll
            for (int i = 0; i < 8; i++)
                pf[i] = *(const uint4*)(in + (size_t)(rowbase + rb0 + 16 * i) * EMB +
                                        (kc + 1) * 64 + qf * 4);
        }
        __syncthreads();

        uint32_t af[4][4];
#pragma unroll
        for (int ks = 0; ks < 4; ks++)
            ldmx4(af[ks], a_base + ((ks * 32 + a_kb) ^ a_x));

#pragma unroll
        for (int nt2 = 0; nt2 < 4; nt2++) {
#pragma unroll
            for (int ks = 0; ks < 4; ks++) {
                uint32_t bf[4];
                int kbyte = kc * 128 + ks * 32 + b_kb;
                ldmx4(bf, sR + (nt2 * 16 + b_nl) * 1024 + (kbyte ^ b_x));
                mma16816(acc[nt2 * 2],     af[ks], bf[0], bf[1]);
                mma16816(acc[nt2 * 2 + 1], af[ks], bf[2], bf[3]);
            }
        }
    }

    const int g = lane >> 2, qd = lane & 3;
    const float sc = 1.0f / 64.0f;
    uint32_t lo[8], hi[8];
#pragma unroll
    for (int nt = 0; nt < 8; nt++) {
        lo[nt] = bf2u(__floats2bfloat162_rn(acc[nt][0] * sc, acc[nt][1] * sc));
        hi[nt] = bf2u(__floats2bfloat162_rn(acc[nt][2] * sc, acc[nt][3] * sc));
        int col = nt * 8 + qd * 2;
        *(uint32_t*)(outp + (size_t)(rowbase + warp * 16 + g) * RD + col)     = lo[nt];
        *(uint32_t*)(outp + (size_t)(rowbase + warp * 16 + g + 8) * RD + col) = hi[nt];
    }

    if (isB) {
        // Fragment-major rb: tile t (8 rows), per (t, lane=g*4+qd) word w=nt.
        // b0 of k-step s = word 2s, b1 = word 2s+1 (PTX m16n8k16 B layout).
        const int t0 = (rowbase >> 3) + warp * 2;   // rows g -> t0; rows g+8 -> t0+1
        char* fp = (char*)g_rbf + (size_t)t0 * 1024 + lane * 32;
        *(uint4*)(fp)        = make_uint4(lo[0], lo[1], lo[2], lo[3]);
        *(uint4*)(fp + 16)   = make_uint4(lo[4], lo[5], lo[6], lo[7]);
        *(uint4*)(fp + 1024) = make_uint4(hi[0], hi[1], hi[2], hi[3]);
        *(uint4*)(fp + 1040) = make_uint4(hi[4], hi[5], hi[6], hi[7]);

#pragma unroll
        for (int i = 0; i < 8; i++) {
            unsigned v = nzf[i];
            v |= __shfl_xor_sync(0xffffffffu, v, 1);
            v |= __shfl_xor_sync(0xffffffffu, v, 2);
            v |= __shfl_xor_sync(0xffffffffu, v, 4);
            v |= __shfl_xor_sync(0xffffffffu, v, 8);
            nzf[i] = v;
        }
        if (qf == 0) {
#pragma unroll
            for (int i = 0; i < 8; i++)
                g_maskmul[rowbase + rb0 + 16 * i] = nzf[i] ? 1.0f : 0.0f;
        }
    }
}

// ---------------------------------------------------------------------------
// sums1: partial M = sum_l mul*rb*rb^T (64x64), v = sum_l mul*rb, N = sum mul
// ---------------------------------------------------------------------------
__global__ __launch_bounds__(256) void sums1_kernel() {
    __shared__ float s_rbm[128][68];
    __shared__ float s_mul[128];
    const int tid = threadIdx.x;
    const int bl = blockIdx.x, batch = blockIdx.y;
    const int l0 = bl * 128;
    const __nv_bfloat16* grb = g_rb + ((size_t)batch * NK + l0) * RD;

    if (tid < 128) s_mul[tid] = g_maskmul[batch * NK + l0 + tid];
    __syncthreads();

#pragma unroll
    for (int t = 0; t < 16; t++) {
        int id = tid + t * 256;
        int l = id >> 5, j2 = id & 31;
        __nv_bfloat162 v = *(const __nv_bfloat162*)(grb + (size_t)l * RD + j2 * 2);
        float m = s_mul[l];
        float2 f = __bfloat1622float2(v);
        s_rbm[l][j2 * 2]     = f.x * m;
        s_rbm[l][j2 * 2 + 1] = f.y * m;
    }
    __syncthreads();

    const int ti = tid >> 4, tj = tid & 15;
    float acc[4][4];
#pragma unroll
    for (int i = 0; i < 4; i++)
#pragma unroll
        for (int j = 0; j < 4; j++) acc[i][j] = 0.f;
    float vacc[4] = {0.f, 0.f, 0.f, 0.f};

#pragma unroll 4
    for (int l = 0; l < 128; l++) {
        float4 bi = *(const float4*)&s_rbm[l][ti * 4];
        float4 bj = *(const float4*)&s_rbm[l][tj * 4];
        float bia[4] = {bi.x, bi.y, bi.z, bi.w};
        float bja[4] = {bj.x, bj.y, bj.z, bj.w};
#pragma unroll
        for (int i = 0; i < 4; i++)
#pragma unroll
            for (int j = 0; j < 4; j++) acc[i][j] += bia[i] * bja[j];
        if (ti == 0) {
            vacc[0] += bja[0]; vacc[1] += bja[1]; vacc[2] += bja[2]; vacc[3] += bja[3];
        }
    }

    float* mp = g_Mpart + (((size_t)batch * 16 + bl) * 64 + ti * 4) * 64 + tj * 4;
#pragma unroll
    for (int i = 0; i < 4; i++)
        *(float4*)(mp + i * 64) = make_float4(acc[i][0], acc[i][1], acc[i][2], acc[i][3]);
    if (ti == 0)
        *(float4*)(g_vpart + ((size_t)batch * 16 + bl) * 64 + tj * 4) =
            make_float4(vacc[0], vacc[1], vacc[2], vacc[3]);
    if (tid == 0) {
        float n = 0.f;
        for (int l = 0; l < 128; l++) n += s_mul[l];
        g_Npart[batch * 16 + bl] = n;
    }
}

// ---------------------------------------------------------------------------
// sums2: reduce partials -> g_Mf (bf16, pre-swizzled), g_v, g_N
// ---------------------------------------------------------------------------
__global__ __launch_bounds__(256) void sums2_kernel() {
    const int batch = blockIdx.x, tid = threadIdx.x;
    const float* mp = g_Mpart + (size_t)batch * 16 * 4096;
#pragma unroll
    for (int t = 0; t < 16; t++) {
        int id = tid + t * 256;
        int c = id >> 6, ik = id & 63;
        float s = 0.f;
#pragma unroll
        for (int p = 0; p < 16; p++) s += mp[(size_t)p * 4096 + c * 64 + ik];
        *(__nv_bfloat16*)(g_Mf + (size_t)batch * 8192 + c * 128 +
                          ((2 * ik) ^ ((c & 7) * 16))) = __float2bfloat16(s);
    }
    if (tid < 64) {
        float s = 0.f;
#pragma unroll
        for (int p = 0; p < 16; p++) s += g_vpart[((size_t)batch * 16 + p) * 64 + tid];
        g_v[batch * 64 + tid] = s;
    }
    if (tid == 64) {
        float s = 0.f;
#pragma unroll
        for (int p = 0; p < 16; p++) s += g_Npart[batch * 16 + p];
        g_N[batch] = s;
    }
}

// ---------------------------------------------------------------------------
// Scores + softmax, single pass, NO smem B path. CTA: 128 rows x 512 cols,
// 256 thr. Warp (wm 0..3, wn 0..1) owns m32 x n256; loops 8 blocks of n32.
// B loaded per block straight from g_rbf (L2-resident) with 8 LDG.128 ->
// fragment registers; ZERO __syncthreads in the main loop (warps free-run).
// Analytic denominators (M prologue via smem ldmatrix); poly-2 softmax.
// ---------------------------------------------------------------------------
__global__ __launch_bounds__(256, 2) void scores_kernel(float* __restrict__ out) {
    __shared__ __align__(16) char s_ra[16384];
    __shared__ __align__(16) char s_M[8192];
    __shared__ float s_mul[512];
    __shared__ float s_v[64];
    const uint32_t sRA = smem_u32(s_ra);
    const uint32_t sM  = smem_u32(s_M);
    const int tid = threadIdx.x, lane = tid & 31, warp = tid >> 5;
    const int wm = warp >> 1, wn = warp & 1;
    const int batch = blockIdx.y;
    const int k1base = (blockIdx.x >> 2) * 128;
    const int nq = blockIdx.x & 3;                  // column quarter [nq*512, +512)

    const __nv_bfloat16* gra = g_ra + ((size_t)batch * NK + k1base) * RD;

    const int rb8 = tid >> 3;        // 0..31
    const int q8  = tid & 7;
    const int x8  = (rb8 & 7) * 16;

    // ra tile: 128 rows x 128B, sw128
#pragma unroll
    for (int i = 0; i < 4; i++) {
        int row = rb8 + 32 * i;
        *(uint4*)(s_ra + row * 128 + ((q8 * 16) ^ x8)) =
            *(const uint4*)(gra + (size_t)row * RD + q8 * 8);
    }
    // mul (this quarter's 512 floats)
    *(float2*)(s_mul + tid * 2) =
        *(const float2*)(g_maskmul + (size_t)batch * NK + nq * 512 + tid * 2);
    // M tile (8 KB, pre-swizzled linear copy)
    {
        const uint4* src = (const uint4*)(g_Mf + (size_t)batch * 8192);
        ((uint4*)s_M)[tid]       = src[tid];
        ((uint4*)s_M)[tid + 256] = src[tid + 256];
    }
    if (tid < 64) s_v[tid] = g_v[batch * 64 + tid];
    __syncthreads();   // the ONLY CTA-wide barrier

    // Persistent A fragments: m32 x k64 (2 m16 tiles)
    uint32_t af[2][4][4];
#pragma unroll
    for (int m = 0; m < 2; m++) {
        const int a_row = wm * 32 + m * 16 + (lane & 15);
        const uint32_t ab = sRA + a_row * 128;
        const int ax = (a_row & 7) * 16;
        const int akb = (lane >> 4) * 16;
#pragma unroll
        for (int ks = 0; ks < 4; ks++) ldmx4(af[m][ks], ab + ((ks * 32 + akb) ^ ax));
    }

    const int b_m = lane >> 3, b_r = lane & 7;
    const int b_nl = (b_m >> 1) * 8 + b_r;
    const int b_kb = (b_m & 1) * 16;
    const int b_x  = b_r * 16;
    const int g = lane >> 2, qd = lane & 3;

    // Denominators: m-serial. W = ra[m16] x M (n64) via ldmatrix on s_M.
    float inv[2][2];
    const float Nb = g_N[batch];
#pragma unroll
    for (int m = 0; m < 2; m++) {
        float wacc[8][4];
#pragma unroll
        for (int t = 0; t < 8; t++) {
            wacc[t][0] = 0.f; wacc[t][1] = 0.f; wacc[t][2] = 0.f; wacc[t][3] = 0.f;
        }
#pragma unroll
        for (int nt2 = 0; nt2 < 4; nt2++) {
#pragma unroll
            for (int ks = 0; ks < 4; ks++) {
                uint32_t bf[4];
                ldmx4(bf, sM + (nt2 * 16 + b_nl) * 128 + ((ks * 32 + b_kb) ^ b_x));
                mma16816(wacc[nt2 * 2],     af[m][ks], bf[0], bf[1]);
                mma16816(wacc[nt2 * 2 + 1], af[m][ks], bf[2], bf[3]);
            }
        }
        float q0 = 0.f, q8v = 0.f;
        const int r0 = wm * 32 + m * 16 + g;
#pragma unroll
        for (int nt = 0; nt < 8; nt++) {
            int c0 = nt * 8 + qd * 2;
            float2 vv = *(const float2*)&s_v[c0];
            uint32_t ru0 = *(const uint32_t*)(s_ra + r0 * 128 +
                                              ((2 * c0) ^ ((r0 & 7) * 16)));
            uint32_t ru8 = *(const uint32_t*)(s_ra + (r0 + 8) * 128 +
                                              ((2 * c0) ^ (((r0 + 8) & 7) * 16)));
            float2 f0 = __bfloat1622float2(*(__nv_bfloat162*)&ru0);
            float2 f8 = __bfloat1622float2(*(__nv_bfloat162*)&ru8);
            q0  += f0.x * fmaf(wacc[nt][0], 0.5f, vv.x) +
                   f0.y * fmaf(wacc[nt][1], 0.5f, vv.y);
            q8v += f8.x * fmaf(wacc[nt][2], 0.5f, vv.x) +
                   f8.y * fmaf(wacc[nt][3], 0.5f, vv.y);
        }
        q0  += __shfl_xor_sync(0xffffffffu, q0, 1);
        q0  += __shfl_xor_sync(0xffffffffu, q0, 2);
        q8v += __shfl_xor_sync(0xffffffffu, q8v, 1);
        q8v += __shfl_xor_sync(0xffffffffu, q8v, 2);
        inv[m][0] = 1.0f / (Nb + q0);
        inv[m][1] = 1.0f / (Nb + q8v);
    }

    // -------- Main loop: no barriers, B straight from global fragments ------
    // Warp's tiles: batch*256 + nq*64 + wn*32 + blk*4 + tt
    const char* fbase = (const char*)g_rbf +
                        ((size_t)batch * 256 + nq * 64 + wn * 32) * 1024 + lane * 32;
    float* ob = out + ((size_t)batch * NK + k1base + wm * 32 + g) * NK +
                nq * 512 + wn * 256;

    for (int blk = 0; blk < 8; blk++) {
        // Load all B for this n32 block: 4 tiles x 2 LDG.128 (k64 each)
        uint4 bt[4][2];
        const char* tp = fbase + (size_t)blk * 4096;
#pragma unroll
        for (int tt = 0; tt < 4; tt++) {
            bt[tt][0] = *(const uint4*)(tp + tt * 1024);
            bt[tt][1] = *(const uint4*)(tp + tt * 1024 + 16);
        }

        float acc[2][4][4];
#pragma unroll
        for (int m = 0; m < 2; m++)
#pragma unroll
            for (int t = 0; t < 4; t++) {
                acc[m][t][0] = 0.f; acc[m][t][1] = 0.f;
                acc[m][t][2] = 0.f; acc[m][t][3] = 0.f;
            }
#pragma unroll
        for (int tt = 0; tt < 4; tt++) {
            // k-steps s: b0 = word 2s, b1 = word 2s+1
#pragma unroll
            for (int m = 0; m < 2; m++) {
                mma16816(acc[m][tt], af[m][0], bt[tt][0].x, bt[tt][0].y);
                mma16816(acc[m][tt], af[m][1], bt[tt][0].z, bt[tt][0].w);
                mma16816(acc[m][tt], af[m][2], bt[tt][1].x, bt[tt][1].y);
                mma16816(acc[m][tt], af[m][3], bt[tt][1].z, bt[tt][1].w);
            }
        }

        // Epilogue: poly-2 + mask + normalize, direct stores
#pragma unroll
        for (int m = 0; m < 2; m++) {
            float* o0 = ob + (size_t)(m * 16) * NK;
            float* o8 = o0 + (size_t)8 * NK;
            const float i0 = inv[m][0], i8 = inv[m][1];
#pragma unroll
            for (int tt = 0; tt < 4; tt++) {
                int colbase = blk * 32 + tt * 8 + qd * 2;
                float2 m2 = *(const float2*)&s_mul[wn * 256 + colbase];
                float s00 = acc[m][tt][0], s01 = acc[m][tt][1];
                float s80 = acc[m][tt][2], s81 = acc[m][tt][3];
                float p00 = fmaf(s00, fmaf(s00, 0.5f, 1.f), 1.f) * m2.x * i0;
                float p01 = fmaf(s01, fmaf(s01, 0.5f, 1.f), 1.f) * m2.y * i0;
                float p80 = fmaf(s80, fmaf(s80, 0.5f, 1.f), 1.f) * m2.x * i8;
                float p81 = fmaf(s81, fmaf(s81, 0.5f, 1.f), 1.f) * m2.y * i8;
                *(float2*)(o0 + colbase) = make_float2(p00, p01);
                *(float2*)(o8 + colbase) = make_float2(p80, p81);
            }
        }
    }
}

// ---------------------------------------------------------------------------
extern "C" void kernel_launch(void* const* d_in, const int* in_sizes, int n_in,
                              void* d_out, int out_size) {
    const float* A  = (const float*)d_in[0];
    const float* Bm = (const float*)d_in[1];
    const float* R  = (const float*)d_in[2];
    // d_in[3] = b: softmax-invariant, unused
    float* out = (float*)d_out;
    (void)in_sizes; (void)n_in; (void)out_size;

    cudaFuncSetAttribute(project_kernel,
                         cudaFuncAttributeMaxDynamicSharedMemorySize, PSMEM);

    project_kernel<<<dim3(128, 2), 256, PSMEM>>>(A, Bm, R);
    sums1_kernel<<<dim3(16, 8), 256>>>();
    sums2_kernel<<<8, 256>>>();
    scores_kernel<<<dim3(64, 8), 256>>>(out);
}

// round 15
// speedup vs baseline: 1.1496x; 1.1496x over previous
#include <cuda_runtime.h>
#include <cuda_bf16.h>
#include <math.h>
#include <stdint.h>

#define BATCH 8
#define NK    2048
#define EMB   512
#define RD    64

// ---------------------------------------------------------------------------
// Scratch globals (allocation-free rule)
// ---------------------------------------------------------------------------
__device__ __nv_bfloat16 g_ra[BATCH * NK * RD];     // 2 MB, scaled by 1/64
__device__ __nv_bfloat16 g_rb[BATCH * NK * RD];     // 2 MB
__device__ float g_maskmul[BATCH * NK];             // 1.0 valid, 0.0 masked
__device__ float g_Mpart[BATCH * 16 * 64 * 64];     // partial M per (batch, lblock)
__device__ float g_vpart[BATCH * 16 * 64];          // partial v
__device__ float g_Npart[BATCH * 16];               // partial counts
__device__ unsigned char g_Mf[BATCH * 64 * 128];    // M bf16, [c][k] 128B rows, pre-swizzled
__device__ float g_v[BATCH * 64];
__device__ float g_N[BATCH];
__device__ int g_cnt[BATCH];                        // zero-init; reset by last CTA

// ---------------------------------------------------------------------------
// Helpers
// ---------------------------------------------------------------------------
__device__ __forceinline__ uint32_t smem_u32(const void* p) {
    uint32_t a;
    asm("{ .reg .u64 t; cvta.to.shared.u64 t, %1; cvt.u32.u64 %0, t; }" : "=r"(a) : "l"(p));
    return a;
}
__device__ __forceinline__ void ldmx4(uint32_t (&r)[4], uint32_t a) {
    asm volatile("ldmatrix.sync.aligned.m8n8.x4.shared.b16 {%0,%1,%2,%3}, [%4];"
                 : "=r"(r[0]), "=r"(r[1]), "=r"(r[2]), "=r"(r[3]) : "r"(a));
}
__device__ __forceinline__ void mma16816(float (&d)[4], const uint32_t (&a)[4],
                                         uint32_t b0, uint32_t b1) {
    asm volatile("mma.sync.aligned.m16n8k16.row.col.f32.bf16.bf16.f32 "
                 "{%0,%1,%2,%3},{%4,%5,%6,%7},{%8,%9},{%0,%1,%2,%3};"
                 : "+f"(d[0]), "+f"(d[1]), "+f"(d[2]), "+f"(d[3])
                 : "r"(a[0]), "r"(a[1]), "r"(a[2]), "r"(a[3]), "r"(b0), "r"(b1));
}
__device__ __forceinline__ uint32_t bf2u(__nv_bfloat162 v) {
    return *reinterpret_cast<uint32_t*>(&v);
}
__device__ __forceinline__ void cp_async16(uint32_t dst, const void* src) {
    asm volatile("cp.async.ca.shared.global [%0], [%1], 16;" :: "r"(dst), "l"(src) : "memory");
}
__device__ __forceinline__ void cp_commit() {
    asm volatile("cp.async.commit_group;" ::: "memory");
}
__device__ __forceinline__ void cp_wait0() {
    asm volatile("cp.async.wait_group 0;" ::: "memory");
}

// ---------------------------------------------------------------------------
// Projection via HMMA: out[row][n] = (1/64) * sum_k in[row][k] * R[k][n]
// A tile double-buffered: ONE __syncthreads per k-chunk (was two).
// Fuses padding-mask (1.0/0.0 multiplier) on the Bm pass.
// ---------------------------------------------------------------------------
#define PSMEM (65536 + 32768)

__global__ __launch_bounds__(256, 2) void project_kernel(const float* __restrict__ A,
                                                         const float* __restrict__ Bm,
                                                         const float* __restrict__ R) {
    extern __shared__ char ps[];
    char* s_R = ps;                 // 64 KB: [n][k] bf16, 1024B rows, sw (2k ^ ((n&7)*16))
    char* s_a = ps + 65536;         // 2 x 16 KB double buffer
    const uint32_t sR = smem_u32(s_R);
    const uint32_t sA = smem_u32(s_a);
    const int tid = threadIdx.x, lane = tid & 31, warp = tid >> 5;
    const int isB = blockIdx.y;
    const float* in = isB ? Bm : A;
    __nv_bfloat16* outp = isB ? g_rb : g_ra;
    const int rowbase = blockIdx.x * 128;

    // Convert R directly into swizzled smem
    {
        const int rn = tid & 63;
        const int rkq = tid >> 6;
        const int xn = (rn & 7) * 16;
#pragma unroll
        for (int t = 0; t < 16; t++) {
            int k = rkq * 128 + t * 8;
            float f0 = R[(size_t)(k + 0) * 64 + rn], f1 = R[(size_t)(k + 1) * 64 + rn];
            float f2 = R[(size_t)(k + 2) * 64 + rn], f3 = R[(size_t)(k + 3) * 64 + rn];
            float f4 = R[(size_t)(k + 4) * 64 + rn], f5 = R[(size_t)(k + 5) * 64 + rn];
            float f6 = R[(size_t)(k + 6) * 64 + rn], f7 = R[(size_t)(k + 7) * 64 + rn];
            uint4 pk;
            pk.x = bf2u(__floats2bfloat162_rn(f0, f1));
            pk.y = bf2u(__floats2bfloat162_rn(f2, f3));
            pk.z = bf2u(__floats2bfloat162_rn(f4, f5));
            pk.w = bf2u(__floats2bfloat162_rn(f6, f7));
            *(uint4*)(s_R + rn * 1024 + ((2 * k) ^ xn)) = pk;
        }
    }

    const int rb0 = tid >> 4;
    const int qf  = tid & 15;
    const int axf = (rb0 & 7) * 16;

    uint4 pf[8];
    unsigned nzf[8];
#pragma unroll
    for (int i = 0; i < 8; i++) nzf[i] = 0u;
#pragma unroll
    for (int i = 0; i < 8; i++)
        pf[i] = *(const uint4*)(in + (size_t)(rowbase + rb0 + 16 * i) * EMB + qf * 4);

    float acc[8][4];
#pragma unroll
    for (int nt = 0; nt < 8; nt++)
#pragma unroll
        for (int j = 0; j < 4; j++) acc[nt][j] = 0.f;

    const int a_row = warp * 16 + (lane & 15);
    const int a_x  = (a_row & 7) * 16;
    const int a_kb = (lane >> 4) * 16;
    const int b_m = lane >> 3, b_r = lane & 7;
    const int b_nl = (b_m >> 1) * 8 + b_r;
    const int b_kb = (b_m & 1) * 16;
    const int b_x  = b_r * 16;

    for (int kc = 0; kc < 8; kc++) {
        char* sab = s_a + (kc & 1) * 16384;
        // Store current chunk (safe vs iter kc-2 reads: iter kc-1 barrier between)
#pragma unroll
        for (int i = 0; i < 8; i++) {
            int row = rb0 + 16 * i;
            float4 v = *(float4*)&pf[i];
            nzf[i] |= (__float_as_uint(v.x) | __float_as_uint(v.y) |
                       __float_as_uint(v.z) | __float_as_uint(v.w)) & 0x7FFFFFFFu;
            __nv_bfloat162 p0 = __floats2bfloat162_rn(v.x, v.y);
            __nv_bfloat162 p1 = __floats2bfloat162_rn(v.z, v.w);
            *(uint2*)(sab + row * 128 + ((qf * 8) ^ axf)) = make_uint2(bf2u(p0), bf2u(p1));
        }
        if (kc < 7) {
#pragma unroll
            for (int i = 0; i < 8; i++)
                pf[i] = *(const uint4*)(in + (size_t)(rowbase + rb0 + 16 * i) * EMB +
                                        (kc + 1) * 64 + qf * 4);
        }
        __syncthreads();

        const uint32_t a_base = sA + (kc & 1) * 16384 + a_row * 128;
        uint32_t af[4][4];
#pragma unroll
        for (int ks = 0; ks < 4; ks++)
            ldmx4(af[ks], a_base + ((ks * 32 + a_kb) ^ a_x));

#pragma unroll
        for (int nt2 = 0; nt2 < 4; nt2++) {
#pragma unroll
            for (int ks = 0; ks < 4; ks++) {
                uint32_t bf[4];
                int kbyte = kc * 128 + ks * 32 + b_kb;
                ldmx4(bf, sR + (nt2 * 16 + b_nl) * 1024 + (kbyte ^ b_x));
                mma16816(acc[nt2 * 2],     af[ks], bf[0], bf[1]);
                mma16816(acc[nt2 * 2 + 1], af[ks], bf[2], bf[3]);
            }
        }
    }

    const int g = lane >> 2, qd = lane & 3;
    const float sc = 1.0f / 64.0f;
#pragma unroll
    for (int nt = 0; nt < 8; nt++) {
        int col = nt * 8 + qd * 2;
        __nv_bfloat162 lo = __floats2bfloat162_rn(acc[nt][0] * sc, acc[nt][1] * sc);
        __nv_bfloat162 hi = __floats2bfloat162_rn(acc[nt][2] * sc, acc[nt][3] * sc);
        *(uint32_t*)(outp + (size_t)(rowbase + warp * 16 + g) * RD + col)     = bf2u(lo);
        *(uint32_t*)(outp + (size_t)(rowbase + warp * 16 + g + 8) * RD + col) = bf2u(hi);
    }

    if (isB) {
#pragma unroll
        for (int i = 0; i < 8; i++) {
            unsigned v = nzf[i];
            v |= __shfl_xor_sync(0xffffffffu, v, 1);
            v |= __shfl_xor_sync(0xffffffffu, v, 2);
            v |= __shfl_xor_sync(0xffffffffu, v, 4);
            v |= __shfl_xor_sync(0xffffffffu, v, 8);
            nzf[i] = v;
        }
        if (qf == 0) {
#pragma unroll
            for (int i = 0; i < 8; i++)
                g_maskmul[rowbase + rb0 + 16 * i] = nzf[i] ? 1.0f : 0.0f;
        }
    }
}

// ---------------------------------------------------------------------------
// sums (fused): partial M/v/N per (batch, lblock); the LAST CTA per batch
// (fence + atomic counter) reduces the 16 partials -> g_Mf/g_v/g_N and
// resets the counter (replay-deterministic).
// ---------------------------------------------------------------------------
__global__ __launch_bounds__(256) void sums_kernel() {
    __shared__ float s_rbm[128][68];
    __shared__ float s_mul[128];
    __shared__ int s_last;
    const int tid = threadIdx.x;
    const int bl = blockIdx.x, batch = blockIdx.y;
    const int l0 = bl * 128;
    const __nv_bfloat16* grb = g_rb + ((size_t)batch * NK + l0) * RD;

    if (tid < 128) s_mul[tid] = g_maskmul[batch * NK + l0 + tid];
    __syncthreads();

#pragma unroll
    for (int t = 0; t < 16; t++) {
        int id = tid + t * 256;
        int l = id >> 5, j2 = id & 31;
        __nv_bfloat162 v = *(const __nv_bfloat162*)(grb + (size_t)l * RD + j2 * 2);
        float m = s_mul[l];
        float2 f = __bfloat1622float2(v);
        s_rbm[l][j2 * 2]     = f.x * m;
        s_rbm[l][j2 * 2 + 1] = f.y * m;
    }
    __syncthreads();

    const int ti = tid >> 4, tj = tid & 15;
    float acc[4][4];
#pragma unroll
    for (int i = 0; i < 4; i++)
#pragma unroll
        for (int j = 0; j < 4; j++) acc[i][j] = 0.f;
    float vacc[4] = {0.f, 0.f, 0.f, 0.f};

#pragma unroll 4
    for (int l = 0; l < 128; l++) {
        float4 bi = *(const float4*)&s_rbm[l][ti * 4];
        float4 bj = *(const float4*)&s_rbm[l][tj * 4];
        float bia[4] = {bi.x, bi.y, bi.z, bi.w};
        float bja[4] = {bj.x, bj.y, bj.z, bj.w};
#pragma unroll
        for (int i = 0; i < 4; i++)
#pragma unroll
            for (int j = 0; j < 4; j++) acc[i][j] += bia[i] * bja[j];
        if (ti == 0) {
            vacc[0] += bja[0]; vacc[1] += bja[1]; vacc[2] += bja[2]; vacc[3] += bja[3];
        }
    }

    float* mp = g_Mpart + (((size_t)batch * 16 + bl) * 64 + ti * 4) * 64 + tj * 4;
#pragma unroll
    for (int i = 0; i < 4; i++)
        *(float4*)(mp + i * 64) = make_float4(acc[i][0], acc[i][1], acc[i][2], acc[i][3]);
    if (ti == 0)
        *(float4*)(g_vpart + ((size_t)batch * 16 + bl) * 64 + tj * 4) =
            make_float4(vacc[0], vacc[1], vacc[2], vacc[3]);
    if (tid == 0) {
        float n = 0.f;
        for (int l = 0; l < 128; l++) n += s_mul[l];
        g_Npart[batch * 16 + bl] = n;
    }

    // ---- last-CTA reduction ----
    __threadfence();               // order this thread's partial stores
    __syncthreads();               // all threads' fences done
    if (tid == 0) {
        int old = atomicAdd(&g_cnt[batch], 1);
        s_last = (old == 15);
    }
    __syncthreads();
    if (!s_last) return;
    __threadfence();               // acquire side

    const float* mpb = g_Mpart + (size_t)batch * 16 * 4096;
#pragma unroll
    for (int t = 0; t < 16; t++) {
        int id = tid + t * 256;
        int c = id >> 6, ik = id & 63;
        float s = 0.f;
#pragma unroll
        for (int p = 0; p < 16; p++) s += mpb[(size_t)p * 4096 + c * 64 + ik];
        *(__nv_bfloat16*)(g_Mf + (size_t)batch * 8192 + c * 128 +
                          ((2 * ik) ^ ((c & 7) * 16))) = __float2bfloat16(s);
    }
    if (tid < 64) {
        float s = 0.f;
#pragma unroll
        for (int p = 0; p < 16; p++) s += g_vpart[((size_t)batch * 16 + p) * 64 + tid];
        g_v[batch * 64 + tid] = s;
    }
    if (tid == 64) {
        float s = 0.f;
#pragma unroll
        for (int p = 0; p < 16; p++) s += g_Npart[batch * 16 + p];
        g_N[batch] = s;
    }
    if (tid == 128) g_cnt[batch] = 0;    // reset for next graph replay
}

// ---------------------------------------------------------------------------
// Scores + softmax (EXACT R7 / 37.7us config). CTA: 128 rows x 1024 cols,
// 256 thr, 2 CTAs/SM. Warp (wm, wn) tile m32 x n64 per n128 chunk; cp.async
// double buffer, ONE __syncthreads per chunk. Analytic denominators;
// p = (1 + s + s^2/2) * mul * inv.
// ---------------------------------------------------------------------------
__global__ __launch_bounds__(256, 2) void scores_kernel(float* __restrict__ out) {
    __shared__ __align__(16) char s_ra[16384];
    __shared__ __align__(16) char s_rb[2][16384];   // buf0 holds M during prologue
    __shared__ float s_mul[1024];
    __shared__ float s_v[64];
    const uint32_t sRA = smem_u32(s_ra);
    const uint32_t sRB[2] = {smem_u32(s_rb[0]), smem_u32(s_rb[1])};
    const int tid = threadIdx.x, lane = tid & 31, warp = tid >> 5;
    const int wm = warp >> 1, wn = warp & 1;
    const int batch = blockIdx.y;
    const int k1base = (blockIdx.x >> 1) * 128;
    const int nh = blockIdx.x & 1;                  // column half: cols [nh*1024, +1024)
    const __nv_bfloat16* gra = g_ra + ((size_t)batch * NK + k1base) * RD;
    const __nv_bfloat16* grb = g_rb + ((size_t)batch * NK + nh * 1024) * RD;

    const int rb8 = tid >> 3;
    const int q8  = tid & 7;
    const int x8  = (rb8 & 7) * 16;

    // ra tile (sw128)
#pragma unroll
    for (int i = 0; i < 4; i++) {
        int row = rb8 + 32 * i;
        *(uint4*)(s_ra + row * 128 + ((q8 * 16) ^ x8)) =
            *(const uint4*)(gra + (size_t)row * RD + q8 * 8);
    }
    // mul (this half's 1024 floats)
    *(float4*)(s_mul + tid * 4) =
        *(const float4*)(g_maskmul + (size_t)batch * NK + nh * 1024 + tid * 4);
    // M tile (pre-swizzled linear copy) into buf0
    {
        const uint4* src = (const uint4*)(g_Mf + (size_t)batch * 8192);
        ((uint4*)s_rb[0])[tid]       = src[tid];
        ((uint4*)s_rb[0])[tid + 256] = src[tid + 256];
    }
    if (tid < 64) s_v[tid] = g_v[batch * 64 + tid];
    __syncthreads();

    // Persistent A fragments: m32 x k64 (2 m16 tiles)
    uint32_t af[2][4][4];
#pragma unroll
    for (int m = 0; m < 2; m++) {
        const int a_row = wm * 32 + m * 16 + (lane & 15);
        const uint32_t ab = sRA + a_row * 128;
        const int ax = (a_row & 7) * 16;
        const int akb = (lane >> 4) * 16;
#pragma unroll
        for (int ks = 0; ks < 4; ks++) ldmx4(af[m][ks], ab + ((ks * 32 + akb) ^ ax));
    }

    const int b_m = lane >> 3, b_r = lane & 7;
    const int b_nl = (b_m >> 1) * 8 + b_r;
    const int b_kb = (b_m & 1) * 16;
    const int b_x  = b_r * 16;
    const int g = lane >> 2, qd = lane & 3;

    // W = ra x M (full n64; prologue only)
    float wacc[2][8][4];
#pragma unroll
    for (int m = 0; m < 2; m++)
#pragma unroll
        for (int t = 0; t < 8; t++) {
            wacc[m][t][0] = 0.f; wacc[m][t][1] = 0.f;
            wacc[m][t][2] = 0.f; wacc[m][t][3] = 0.f;
        }
#pragma unroll
    for (int nt2 = 0; nt2 < 4; nt2++) {
#pragma unroll
        for (int ks = 0; ks < 4; ks++) {
            uint32_t bf[4];
            ldmx4(bf, sRB[0] + (nt2 * 16 + b_nl) * 128 + ((ks * 32 + b_kb) ^ b_x));
#pragma unroll
            for (int m = 0; m < 2; m++) {
                mma16816(wacc[m][nt2 * 2],     af[m][ks], bf[0], bf[1]);
                mma16816(wacc[m][nt2 * 2 + 1], af[m][ks], bf[2], bf[3]);
            }
        }
    }
    // q[m][r] = sum_c ra_c * (v_c + 0.5*W_c) for rows wm*32+m*16+{g, g+8}
    float inv[2][2];
#pragma unroll
    for (int m = 0; m < 2; m++) {
        float q0 = 0.f, q8v = 0.f;
        const int r0 = wm * 32 + m * 16 + g;
#pragma unroll
        for (int nt = 0; nt < 8; nt++) {
            int c0 = nt * 8 + qd * 2;
            float2 vv = *(const float2*)&s_v[c0];
            uint32_t ru0 = *(const uint32_t*)(s_ra + r0 * 128 + ((2 * c0) ^ ((r0 & 7) * 16)));
            uint32_t ru8 = *(const uint32_t*)(s_ra + (r0 + 8) * 128 +
                                              ((2 * c0) ^ (((r0 + 8) & 7) * 16)));
            float2 f0 = __bfloat1622float2(*(__nv_bfloat162*)&ru0);
            float2 f8 = __bfloat1622float2(*(__nv_bfloat162*)&ru8);
            q0  += f0.x * fmaf(wacc[m][nt][0], 0.5f, vv.x) +
                   f0.y * fmaf(wacc[m][nt][1], 0.5f, vv.y);
            q8v += f8.x * fmaf(wacc[m][nt][2], 0.5f, vv.x) +
                   f8.y * fmaf(wacc[m][nt][3], 0.5f, vv.y);
        }
        q0  += __shfl_xor_sync(0xffffffffu, q0, 1);
        q0  += __shfl_xor_sync(0xffffffffu, q0, 2);
        q8v += __shfl_xor_sync(0xffffffffu, q8v, 1);
        q8v += __shfl_xor_sync(0xffffffffu, q8v, 2);
        const float Nb = g_N[batch];
        inv[m][0] = 1.0f / (Nb + q0);
        inv[m][1] = 1.0f / (Nb + q8v);
    }

    __syncthreads();   // all warps done reading M in buf0

    // Issue chunk 0 via cp.async into buf0 (1024 x 16B, 4 per thread)
#pragma unroll
    for (int i = 0; i < 4; i++) {
        int row = rb8 + 32 * i;
        cp_async16(sRB[0] + row * 128 + ((q8 * 16) ^ x8),
                   grb + (size_t)row * RD + q8 * 8);
    }
    cp_commit();

    // Output base: row (wm*32 + g), col (nh*1024 + wn*64)
    float* ob = out + ((size_t)batch * NK + k1base + wm * 32 + g) * NK + nh * 1024;

    for (int c = 0; c < 8; c++) {
        const int buf = c & 1;
        cp_wait0();
        __syncthreads();   // chunk c visible; all warps done reading buf^1 (iter c-1)

        if (c < 7) {
#pragma unroll
            for (int i = 0; i < 4; i++) {
                int row = rb8 + 32 * i;
                cp_async16(sRB[buf ^ 1] + row * 128 + ((q8 * 16) ^ x8),
                           grb + (size_t)((c + 1) * 128 + row) * RD + q8 * 8);
            }
            cp_commit();
        }

        float acc[2][8][4];
#pragma unroll
        for (int m = 0; m < 2; m++)
#pragma unroll
            for (int t = 0; t < 8; t++) {
                acc[m][t][0] = 0.f; acc[m][t][1] = 0.f;
                acc[m][t][2] = 0.f; acc[m][t][3] = 0.f;
            }
        // B: this warp's n64 half of the n128 chunk
#pragma unroll
        for (int nt2 = 0; nt2 < 4; nt2++) {
#pragma unroll
            for (int ks = 0; ks < 4; ks++) {
                uint32_t bf[4];
                ldmx4(bf, sRB[buf] + (wn * 64 + nt2 * 16 + b_nl) * 128 +
                          ((ks * 32 + b_kb) ^ b_x));
#pragma unroll
                for (int m = 0; m < 2; m++) {
                    mma16816(acc[m][nt2 * 2],     af[m][ks], bf[0], bf[1]);
                    mma16816(acc[m][nt2 * 2 + 1], af[m][ks], bf[2], bf[3]);
                }
            }
        }

        // Epilogue: rows wm*32 + m*16 + {g, g+8}, cols c*128 + wn*64 + nt*8 + qd*2
#pragma unroll
        for (int m = 0; m < 2; m++) {
            float* o0 = ob + (size_t)(m * 16) * NK;
            float* o8 = o0 + (size_t)8 * NK;
            const float i0 = inv[m][0], i8 = inv[m][1];
#pragma unroll
            for (int nt = 0; nt < 8; nt++) {
                int colbase = c * 128 + wn * 64 + nt * 8 + qd * 2;
                float2 m2 = *(const float2*)&s_mul[colbase];
                float s00 = acc[m][nt][0], s01 = acc[m][nt][1];
                float s80 = acc[m][nt][2], s81 = acc[m][nt][3];
                float p00 = fmaf(s00, fmaf(s00, 0.5f, 1.f), 1.f) * m2.x * i0;
                float p01 = fmaf(s01, fmaf(s01, 0.5f, 1.f), 1.f) * m2.y * i0;
                float p80 = fmaf(s80, fmaf(s80, 0.5f, 1.f), 1.f) * m2.x * i8;
                float p81 = fmaf(s81, fmaf(s81, 0.5f, 1.f), 1.f) * m2.y * i8;
                *(float2*)(o0 + colbase) = make_float2(p00, p01);
                *(float2*)(o8 + colbase) = make_float2(p80, p81);
            }
        }
        // No trailing barrier: next iteration's barrier (after cp_wait0)
        // fences buf reuse; epilogue touches only global + read-only smem.
    }
}

// ---------------------------------------------------------------------------
extern "C" void kernel_launch(void* const* d_in, const int* in_sizes, int n_in,
                              void* d_out, int out_size) {
    const float* A  = (const float*)d_in[0];
    const float* Bm = (const float*)d_in[1];
    const float* R  = (const float*)d_in[2];
    // d_in[3] = b: softmax-invariant, unused
    float* out = (float*)d_out;
    (void)in_sizes; (void)n_in; (void)out_size;

    cudaFuncSetAttribute(project_kernel,
                         cudaFuncAttributeMaxDynamicSharedMemorySize, PSMEM);

    project_kernel<<<dim3(128, 2), 256, PSMEM>>>(A, Bm, R);
    sums_kernel<<<dim3(16, 8), 256>>>();
    scores_kernel<<<dim3(32, 8), 256>>>(out);
}

// round 16
// speedup vs baseline: 1.1502x; 1.0005x over previous
#include <cuda_runtime.h>
#include <cuda_bf16.h>
#include <math.h>
#include <stdint.h>

#define BATCH 8
#define NK    2048
#define EMB   512
#define RD    64

// ---------------------------------------------------------------------------
// Scratch globals (allocation-free rule)
// ---------------------------------------------------------------------------
__device__ __nv_bfloat16 g_ra[BATCH * NK * RD];     // 2 MB, scaled by 1/64
__device__ __nv_bfloat16 g_rb[BATCH * NK * RD];     // 2 MB
__device__ float g_maskmul[BATCH * NK];             // 1.0 valid, 0.0 masked
__device__ float g_Mpart[BATCH * 16 * 64 * 64];     // partial M per (batch, lblock)
__device__ float g_vpart[BATCH * 16 * 64];          // partial v
__device__ float g_Npart[BATCH * 16];               // partial counts
__device__ unsigned char g_Mf[BATCH * 64 * 128];    // M bf16, [c][k] 128B rows, pre-swizzled
__device__ float g_v[BATCH * 64];
__device__ float g_N[BATCH];
__device__ int g_cnt[BATCH];                        // zero-init; reset by last CTA

// ---------------------------------------------------------------------------
// Helpers
// ---------------------------------------------------------------------------
__device__ __forceinline__ uint32_t smem_u32(const void* p) {
    uint32_t a;
    asm("{ .reg .u64 t; cvta.to.shared.u64 t, %1; cvt.u32.u64 %0, t; }" : "=r"(a) : "l"(p));
    return a;
}
__device__ __forceinline__ void ldmx4(uint32_t (&r)[4], uint32_t a) {
    asm volatile("ldmatrix.sync.aligned.m8n8.x4.shared.b16 {%0,%1,%2,%3}, [%4];"
                 : "=r"(r[0]), "=r"(r[1]), "=r"(r[2]), "=r"(r[3]) : "r"(a));
}
__device__ __forceinline__ void mma16816(float (&d)[4], const uint32_t (&a)[4],
                                         uint32_t b0, uint32_t b1) {
    asm volatile("mma.sync.aligned.m16n8k16.row.col.f32.bf16.bf16.f32 "
                 "{%0,%1,%2,%3},{%4,%5,%6,%7},{%8,%9},{%0,%1,%2,%3};"
                 : "+f"(d[0]), "+f"(d[1]), "+f"(d[2]), "+f"(d[3])
                 : "r"(a[0]), "r"(a[1]), "r"(a[2]), "r"(a[3]), "r"(b0), "r"(b1));
}
__device__ __forceinline__ uint32_t bf2u(__nv_bfloat162 v) {
    return *reinterpret_cast<uint32_t*>(&v);
}
__device__ __forceinline__ void cp_async16(uint32_t dst, const void* src) {
    asm volatile("cp.async.ca.shared.global [%0], [%1], 16;" :: "r"(dst), "l"(src) : "memory");
}
__device__ __forceinline__ void cp_commit() {
    asm volatile("cp.async.commit_group;" ::: "memory");
}
__device__ __forceinline__ void cp_wait0() {
    asm volatile("cp.async.wait_group 0;" ::: "memory");
}

// ---------------------------------------------------------------------------
// Projection via HMMA + FUSED sums (B pass).
// out[row][n] = (1/64) * sum_k in[row][k] * R[k][n]
// A tile double-buffered: one __syncthreads per k-chunk.
// B pass: mask, then in-smem sums1 (partial M/v/N from the CTA's own rb tile,
// bf16-rounded & masked — bit-identical to the old sums1 inputs), and the
// last-of-16 CTA per batch reduces partials -> g_Mf/g_v/g_N (resets counter).
// ---------------------------------------------------------------------------
#define PSMEM (65536 + 32768)

__global__ __launch_bounds__(256, 2) void project_kernel(const float* __restrict__ A,
                                                         const float* __restrict__ Bm,
                                                         const float* __restrict__ R) {
    extern __shared__ char ps[];
    char* s_R = ps;                 // 64 KB: [n][k] bf16, 1024B rows, sw (2k ^ ((n&7)*16))
    char* s_a = ps + 65536;         // 2 x 16 KB double buffer
    const uint32_t sR = smem_u32(s_R);
    const uint32_t sA = smem_u32(s_a);
    const int tid = threadIdx.x, lane = tid & 31, warp = tid >> 5;
    const int isB = blockIdx.y;
    const float* in = isB ? Bm : A;
    __nv_bfloat16* outp = isB ? g_rb : g_ra;
    const int rowbase = blockIdx.x * 128;

    // Convert R directly into swizzled smem
    {
        const int rn = tid & 63;
        const int rkq = tid >> 6;
        const int xn = (rn & 7) * 16;
#pragma unroll
        for (int t = 0; t < 16; t++) {
            int k = rkq * 128 + t * 8;
            float f0 = R[(size_t)(k + 0) * 64 + rn], f1 = R[(size_t)(k + 1) * 64 + rn];
            float f2 = R[(size_t)(k + 2) * 64 + rn], f3 = R[(size_t)(k + 3) * 64 + rn];
            float f4 = R[(size_t)(k + 4) * 64 + rn], f5 = R[(size_t)(k + 5) * 64 + rn];
            float f6 = R[(size_t)(k + 6) * 64 + rn], f7 = R[(size_t)(k + 7) * 64 + rn];
            uint4 pk;
            pk.x = bf2u(__floats2bfloat162_rn(f0, f1));
            pk.y = bf2u(__floats2bfloat162_rn(f2, f3));
            pk.z = bf2u(__floats2bfloat162_rn(f4, f5));
            pk.w = bf2u(__floats2bfloat162_rn(f6, f7));
            *(uint4*)(s_R + rn * 1024 + ((2 * k) ^ xn)) = pk;
        }
    }

    const int rb0 = tid >> 4;
    const int qf  = tid & 15;
    const int axf = (rb0 & 7) * 16;

    uint4 pf[8];
    unsigned nzf[8];
#pragma unroll
    for (int i = 0; i < 8; i++) nzf[i] = 0u;
#pragma unroll
    for (int i = 0; i < 8; i++)
        pf[i] = *(const uint4*)(in + (size_t)(rowbase + rb0 + 16 * i) * EMB + qf * 4);

    float acc[8][4];
#pragma unroll
    for (int nt = 0; nt < 8; nt++)
#pragma unroll
        for (int j = 0; j < 4; j++) acc[nt][j] = 0.f;

    const int a_row = warp * 16 + (lane & 15);
    const int a_x  = (a_row & 7) * 16;
    const int a_kb = (lane >> 4) * 16;
    const int b_m = lane >> 3, b_r = lane & 7;
    const int b_nl = (b_m >> 1) * 8 + b_r;
    const int b_kb = (b_m & 1) * 16;
    const int b_x  = b_r * 16;

    for (int kc = 0; kc < 8; kc++) {
        char* sab = s_a + (kc & 1) * 16384;
#pragma unroll
        for (int i = 0; i < 8; i++) {
            int row = rb0 + 16 * i;
            float4 v = *(float4*)&pf[i];
            nzf[i] |= (__float_as_uint(v.x) | __float_as_uint(v.y) |
                       __float_as_uint(v.z) | __float_as_uint(v.w)) & 0x7FFFFFFFu;
            __nv_bfloat162 p0 = __floats2bfloat162_rn(v.x, v.y);
            __nv_bfloat162 p1 = __floats2bfloat162_rn(v.z, v.w);
            *(uint2*)(sab + row * 128 + ((qf * 8) ^ axf)) = make_uint2(bf2u(p0), bf2u(p1));
        }
        if (kc < 7) {
#pragma unroll
            for (int i = 0; i < 8; i++)
                pf[i] = *(const uint4*)(in + (size_t)(rowbase + rb0 + 16 * i) * EMB +
                                        (kc + 1) * 64 + qf * 4);
        }
        __syncthreads();

        const uint32_t a_base = sA + (kc & 1) * 16384 + a_row * 128;
        uint32_t af[4][4];
#pragma unroll
        for (int ks = 0; ks < 4; ks++)
            ldmx4(af[ks], a_base + ((ks * 32 + a_kb) ^ a_x));

#pragma unroll
        for (int nt2 = 0; nt2 < 4; nt2++) {
#pragma unroll
            for (int ks = 0; ks < 4; ks++) {
                uint32_t bf[4];
                int kbyte = kc * 128 + ks * 32 + b_kb;
                ldmx4(bf, sR + (nt2 * 16 + b_nl) * 1024 + (kbyte ^ b_x));
                mma16816(acc[nt2 * 2],     af[ks], bf[0], bf[1]);
                mma16816(acc[nt2 * 2 + 1], af[ks], bf[2], bf[3]);
            }
        }
    }

    const int g = lane >> 2, qd = lane & 3;
    const float sc = 1.0f / 64.0f;
    uint32_t lo[8], hi[8];
#pragma unroll
    for (int nt = 0; nt < 8; nt++) {
        int col = nt * 8 + qd * 2;
        lo[nt] = bf2u(__floats2bfloat162_rn(acc[nt][0] * sc, acc[nt][1] * sc));
        hi[nt] = bf2u(__floats2bfloat162_rn(acc[nt][2] * sc, acc[nt][3] * sc));
        *(uint32_t*)(outp + (size_t)(rowbase + warp * 16 + g) * RD + col)     = lo[nt];
        *(uint32_t*)(outp + (size_t)(rowbase + warp * 16 + g + 8) * RD + col) = hi[nt];
    }

    if (!isB) return;

    // ======================= Fused sums (B pass only) =======================
    const int batch = blockIdx.x >> 4;      // 16 CTAs per batch
    const int bl    = blockIdx.x & 15;

    // Mask reduction; publish per-row mul to global AND smem.
    float* s_mulrow = (float*)(ps + 40960);         // 128 floats (inside dead s_R)
    float* s_rbm    = (float*)(ps + 45056);         // [128][68] fp32 = 34816 B
    __syncthreads();   // all s_R / s_a reads done before reuse

#pragma unroll
    for (int i = 0; i < 8; i++) {
        unsigned v = nzf[i];
        v |= __shfl_xor_sync(0xffffffffu, v, 1);
        v |= __shfl_xor_sync(0xffffffffu, v, 2);
        v |= __shfl_xor_sync(0xffffffffu, v, 4);
        v |= __shfl_xor_sync(0xffffffffu, v, 8);
        nzf[i] = v;
    }
    if (qf == 0) {
#pragma unroll
        for (int i = 0; i < 8; i++) {
            float m = nzf[i] ? 1.0f : 0.0f;
            g_maskmul[rowbase + rb0 + 16 * i] = m;
            s_mulrow[rb0 + 16 * i] = m;
        }
    }
    __syncthreads();

    // Write this CTA's rb tile (bf16-rounded, masked) to smem fp32 [128][68].
    {
        const int r0 = warp * 16 + g, r8 = r0 + 8;
        const float m0 = s_mulrow[r0], m8 = s_mulrow[r8];
#pragma unroll
        for (int nt = 0; nt < 8; nt++) {
            int col = nt * 8 + qd * 2;
            float2 f0 = __bfloat1622float2(*(__nv_bfloat162*)&lo[nt]);
            float2 f8 = __bfloat1622float2(*(__nv_bfloat162*)&hi[nt]);
            s_rbm[r0 * 68 + col]     = f0.x * m0;
            s_rbm[r0 * 68 + col + 1] = f0.y * m0;
            s_rbm[r8 * 68 + col]     = f8.x * m8;
            s_rbm[r8 * 68 + col + 1] = f8.y * m8;
        }
    }
    __syncthreads();

    // Partial M (64x64), v, N over the 128 rows.
    {
        const int ti = tid >> 4, tj = tid & 15;
        float macc[4][4];
#pragma unroll
        for (int i = 0; i < 4; i++)
#pragma unroll
            for (int j = 0; j < 4; j++) macc[i][j] = 0.f;
        float vacc[4] = {0.f, 0.f, 0.f, 0.f};

#pragma unroll 4
        for (int l = 0; l < 128; l++) {
            float4 bi = *(const float4*)&s_rbm[l * 68 + ti * 4];
            float4 bj = *(const float4*)&s_rbm[l * 68 + tj * 4];
            float bia[4] = {bi.x, bi.y, bi.z, bi.w};
            float bja[4] = {bj.x, bj.y, bj.z, bj.w};
#pragma unroll
            for (int i = 0; i < 4; i++)
#pragma unroll
                for (int j = 0; j < 4; j++) macc[i][j] += bia[i] * bja[j];
            if (ti == 0) {
                vacc[0] += bja[0]; vacc[1] += bja[1];
                vacc[2] += bja[2]; vacc[3] += bja[3];
            }
        }

        float* mp = g_Mpart + (((size_t)batch * 16 + bl) * 64 + ti * 4) * 64 + tj * 4;
#pragma unroll
        for (int i = 0; i < 4; i++)
            *(float4*)(mp + i * 64) =
                make_float4(macc[i][0], macc[i][1], macc[i][2], macc[i][3]);
        if (ti == 0)
            *(float4*)(g_vpart + ((size_t)batch * 16 + bl) * 64 + tj * 4) =
                make_float4(vacc[0], vacc[1], vacc[2], vacc[3]);
        if (tid == 0) {
            float n = 0.f;
            for (int l = 0; l < 128; l++) n += s_mulrow[l];
            g_Npart[batch * 16 + bl] = n;
        }
    }

    // Last-of-16 CTA per batch reduces partials.
    __shared__ int s_last;
    __threadfence();
    __syncthreads();
    if (tid == 0) {
        int old = atomicAdd(&g_cnt[batch], 1);
        s_last = (old == 15);
    }
    __syncthreads();
    if (!s_last) return;
    __threadfence();

    const float* mpb = g_Mpart + (size_t)batch * 16 * 4096;
#pragma unroll
    for (int t = 0; t < 16; t++) {
        int id = tid + t * 256;
        int c = id >> 6, ik = id & 63;
        float s = 0.f;
#pragma unroll
        for (int p = 0; p < 16; p++) s += mpb[(size_t)p * 4096 + c * 64 + ik];
        *(__nv_bfloat16*)(g_Mf + (size_t)batch * 8192 + c * 128 +
                          ((2 * ik) ^ ((c & 7) * 16))) = __float2bfloat16(s);
    }
    if (tid < 64) {
        float s = 0.f;
#pragma unroll
        for (int p = 0; p < 16; p++) s += g_vpart[((size_t)batch * 16 + p) * 64 + tid];
        g_v[batch * 64 + tid] = s;
    }
    if (tid == 64) {
        float s = 0.f;
#pragma unroll
        for (int p = 0; p < 16; p++) s += g_Npart[batch * 16 + p];
        g_N[batch] = s;
    }
    if (tid == 128) g_cnt[batch] = 0;    // reset for next graph replay
}

// ---------------------------------------------------------------------------
// Scores + softmax (EXACT R7 / 37.7us config). CTA: 128 rows x 1024 cols,
// 256 thr, 2 CTAs/SM. Warp (wm, wn) tile m32 x n64 per n128 chunk; cp.async
// double buffer, ONE __syncthreads per chunk. Analytic denominators;
// p = (1 + s + s^2/2) * mul * inv.
// ---------------------------------------------------------------------------
__global__ __launch_bounds__(256, 2) void scores_kernel(float* __restrict__ out) {
    __shared__ __align__(16) char s_ra[16384];
    __shared__ __align__(16) char s_rb[2][16384];   // buf0 holds M during prologue
    __shared__ float s_mul[1024];
    __shared__ float s_v[64];
    const uint32_t sRA = smem_u32(s_ra);
    const uint32_t sRB[2] = {smem_u32(s_rb[0]), smem_u32(s_rb[1])};
    const int tid = threadIdx.x, lane = tid & 31, warp = tid >> 5;
    const int wm = warp >> 1, wn = warp & 1;
    const int batch = blockIdx.y;
    const int k1base = (blockIdx.x >> 1) * 128;
    const int nh = blockIdx.x & 1;                  // column half: cols [nh*1024, +1024)
    const __nv_bfloat16* gra = g_ra + ((size_t)batch * NK + k1base) * RD;
    const __nv_bfloat16* grb = g_rb + ((size_t)batch * NK + nh * 1024) * RD;

    const int rb8 = tid >> 3;
    const int q8  = tid & 7;
    const int x8  = (rb8 & 7) * 16;

    // ra tile (sw128)
#pragma unroll
    for (int i = 0; i < 4; i++) {
        int row = rb8 + 32 * i;
        *(uint4*)(s_ra + row * 128 + ((q8 * 16) ^ x8)) =
            *(const uint4*)(gra + (size_t)row * RD + q8 * 8);
    }
    // mul (this half's 1024 floats)
    *(float4*)(s_mul + tid * 4) =
        *(const float4*)(g_maskmul + (size_t)batch * NK + nh * 1024 + tid * 4);
    // M tile (pre-swizzled linear copy) into buf0
    {
        const uint4* src = (const uint4*)(g_Mf + (size_t)batch * 8192);
        ((uint4*)s_rb[0])[tid]       = src[tid];
        ((uint4*)s_rb[0])[tid + 256] = src[tid + 256];
    }
    if (tid < 64) s_v[tid] = g_v[batch * 64 + tid];
    __syncthreads();

    // Persistent A fragments: m32 x k64 (2 m16 tiles)
    uint32_t af[2][4][4];
#pragma unroll
    for (int m = 0; m < 2; m++) {
        const int a_row = wm * 32 + m * 16 + (lane & 15);
        const uint32_t ab = sRA + a_row * 128;
        const int ax = (a_row & 7) * 16;
        const int akb = (lane >> 4) * 16;
#pragma unroll
        for (int ks = 0; ks < 4; ks++) ldmx4(af[m][ks], ab + ((ks * 32 + akb) ^ ax));
    }

    const int b_m = lane >> 3, b_r = lane & 7;
    const int b_nl = (b_m >> 1) * 8 + b_r;
    const int b_kb = (b_m & 1) * 16;
    const int b_x  = b_r * 16;
    const int g = lane >> 2, qd = lane & 3;

    // W = ra x M (full n64; prologue only)
    float wacc[2][8][4];
#pragma unroll
    for (int m = 0; m < 2; m++)
#pragma unroll
        for (int t = 0; t < 8; t++) {
            wacc[m][t][0] = 0.f; wacc[m][t][1] = 0.f;
            wacc[m][t][2] = 0.f; wacc[m][t][3] = 0.f;
        }
#pragma unroll
    for (int nt2 = 0; nt2 < 4; nt2++) {
#pragma unroll
        for (int ks = 0; ks < 4; ks++) {
            uint32_t bf[4];
            ldmx4(bf, sRB[0] + (nt2 * 16 + b_nl) * 128 + ((ks * 32 + b_kb) ^ b_x));
#pragma unroll
            for (int m = 0; m < 2; m++) {
                mma16816(wacc[m][nt2 * 2],     af[m][ks], bf[0], bf[1]);
                mma16816(wacc[m][nt2 * 2 + 1], af[m][ks], bf[2], bf[3]);
            }
        }
    }
    // q[m][r] = sum_c ra_c * (v_c + 0.5*W_c) for rows wm*32+m*16+{g, g+8}
    float inv[2][2];
#pragma unroll
    for (int m = 0; m < 2; m++) {
        float q0 = 0.f, q8v = 0.f;
        const int r0 = wm * 32 + m * 16 + g;
#pragma unroll
        for (int nt = 0; nt < 8; nt++) {
            int c0 = nt * 8 + qd * 2;
            float2 vv = *(const float2*)&s_v[c0];
            uint32_t ru0 = *(const uint32_t*)(s_ra + r0 * 128 + ((2 * c0) ^ ((r0 & 7) * 16)));
            uint32_t ru8 = *(const uint32_t*)(s_ra + (r0 + 8) * 128 +
                                              ((2 * c0) ^ (((r0 + 8) & 7) * 16)));
            float2 f0 = __bfloat1622float2(*(__nv_bfloat162*)&ru0);
            float2 f8 = __bfloat1622float2(*(__nv_bfloat162*)&ru8);
            q0  += f0.x * fmaf(wacc[m][nt][0], 0.5f, vv.x) +
                   f0.y * fmaf(wacc[m][nt][1], 0.5f, vv.y);
            q8v += f8.x * fmaf(wacc[m][nt][2], 0.5f, vv.x) +
                   f8.y * fmaf(wacc[m][nt][3], 0.5f, vv.y);
        }
        q0  += __shfl_xor_sync(0xffffffffu, q0, 1);
        q0  += __shfl_xor_sync(0xffffffffu, q0, 2);
        q8v += __shfl_xor_sync(0xffffffffu, q8v, 1);
        q8v += __shfl_xor_sync(0xffffffffu, q8v, 2);
        const float Nb = g_N[batch];
        inv[m][0] = 1.0f / (Nb + q0);
        inv[m][1] = 1.0f / (Nb + q8v);
    }

    __syncthreads();   // all warps done reading M in buf0

    // Issue chunk 0 via cp.async into buf0 (1024 x 16B, 4 per thread)
#pragma unroll
    for (int i = 0; i < 4; i++) {
        int row = rb8 + 32 * i;
        cp_async16(sRB[0] + row * 128 + ((q8 * 16) ^ x8),
                   grb + (size_t)row * RD + q8 * 8);
    }
    cp_commit();

    // Output base: row (wm*32 + g), col (nh*1024 + wn*64)
    float* ob = out + ((size_t)batch * NK + k1base + wm * 32 + g) * NK + nh * 1024;

    for (int c = 0; c < 8; c++) {
        const int buf = c & 1;
        cp_wait0();
        __syncthreads();   // chunk c visible; all warps done reading buf^1 (iter c-1)

        if (c < 7) {
#pragma unroll
            for (int i = 0; i < 4; i++) {
                int row = rb8 + 32 * i;
                cp_async16(sRB[buf ^ 1] + row * 128 + ((q8 * 16) ^ x8),
                           grb + (size_t)((c + 1) * 128 + row) * RD + q8 * 8);
            }
            cp_commit();
        }

        float acc[2][8][4];
#pragma unroll
        for (int m = 0; m < 2; m++)
#pragma unroll
            for (int t = 0; t < 8; t++) {
                acc[m][t][0] = 0.f; acc[m][t][1] = 0.f;
                acc[m][t][2] = 0.f; acc[m][t][3] = 0.f;
            }
        // B: this warp's n64 half of the n128 chunk
#pragma unroll
        for (int nt2 = 0; nt2 < 4; nt2++) {
#pragma unroll
            for (int ks = 0; ks < 4; ks++) {
                uint32_t bf[4];
                ldmx4(bf, sRB[buf] + (wn * 64 + nt2 * 16 + b_nl) * 128 +
                          ((ks * 32 + b_kb) ^ b_x));
#pragma unroll
                for (int m = 0; m < 2; m++) {
                    mma16816(acc[m][nt2 * 2],     af[m][ks], bf[0], bf[1]);
                    mma16816(acc[m][nt2 * 2 + 1], af[m][ks], bf[2], bf[3]);
                }
            }
        }

        // Epilogue: rows wm*32 + m*16 + {g, g+8}, cols c*128 + wn*64 + nt*8 + qd*2
#pragma unroll
        for (int m = 0; m < 2; m++) {
            float* o0 = ob + (size_t)(m * 16) * NK;
            float* o8 = o0 + (size_t)8 * NK;
            const float i0 = inv[m][0], i8 = inv[m][1];
#pragma unroll
            for (int nt = 0; nt < 8; nt++) {
                int colbase = c * 128 + wn * 64 + nt * 8 + qd * 2;
                float2 m2 = *(const float2*)&s_mul[colbase];
                float s00 = acc[m][nt][0], s01 = acc[m][nt][1];
                float s80 = acc[m][nt][2], s81 = acc[m][nt][3];
                float p00 = fmaf(s00, fmaf(s00, 0.5f, 1.f), 1.f) * m2.x * i0;
                float p01 = fmaf(s01, fmaf(s01, 0.5f, 1.f), 1.f) * m2.y * i0;
                float p80 = fmaf(s80, fmaf(s80, 0.5f, 1.f), 1.f) * m2.x * i8;
                float p81 = fmaf(s81, fmaf(s81, 0.5f, 1.f), 1.f) * m2.y * i8;
                *(float2*)(o0 + colbase) = make_float2(p00, p01);
                *(float2*)(o8 + colbase) = make_float2(p80, p81);
            }
        }
        // No trailing barrier: next iteration's barrier (after cp_wait0)
        // fences buf reuse; epilogue touches only global + read-only smem.
    }
}

// ---------------------------------------------------------------------------
extern "C" void kernel_launch(void* const* d_in, const int* in_sizes, int n_in,
                              void* d_out, int out_size) {
    const float* A  = (const float*)d_in[0];
    const float* Bm = (const float*)d_in[1];
    const float* R  = (const float*)d_in[2];
    // d_in[3] = b: softmax-invariant, unused
    float* out = (float*)d_out;
    (void)in_sizes; (void)n_in; (void)out_size;

    cudaFuncSetAttribute(project_kernel,
                         cudaFuncAttributeMaxDynamicSharedMemorySize, PSMEM);

    project_kernel<<<dim3(128, 2), 256, PSMEM>>>(A, Bm, R);
    scores_kernel<<<dim3(32, 8), 256>>>(out);
}